// round 1
// baseline (speedup 1.0000x reference)
#include <cuda_runtime.h>

#define N_NODES 5
#define EMB 16
#define HID 32

// LUT: row c gives the 16-float output row for cells with game_state == c.
// Row 0 = emb_table[0]; rows 1..5 = node_emb[0..4].
__device__ float g_lut[6 * EMB];

__global__ void gcn_precompute_kernel(const float* __restrict__ emb,
                                      const float* __restrict__ A,
                                      const float* __restrict__ W0,
                                      const float* __restrict__ W1,
                                      const float* __restrict__ W2,
                                      const float* __restrict__ Wf,
                                      const float* __restrict__ bf) {
    __shared__ float sA[N_NODES * N_NODES];
    __shared__ float se[N_NODES * EMB];
    __shared__ float x0[N_NODES * EMB];
    __shared__ float xh[N_NODES * HID];
    __shared__ float xt[N_NODES * HID];
    const int t = threadIdx.x;

    if (t < N_NODES * N_NODES) sA[t] = A[t];
    if (t < N_NODES * EMB)     se[t] = emb[t];
    __syncthreads();

    // x0 = A @ emb_table                     [5,16]
    if (t < N_NODES * EMB) {
        const int i = t / EMB, j = t % EMB;
        float s = 0.f;
        #pragma unroll
        for (int k = 0; k < N_NODES; k++) s += sA[i * N_NODES + k] * se[k * EMB + j];
        x0[t] = s;
    }
    __syncthreads();

    // xh = relu(x0 @ W0^T)                   [5,32]
    if (t < N_NODES * HID) {
        const int i = t / HID, o = t % HID;
        float s = 0.f;
        #pragma unroll
        for (int j = 0; j < EMB; j++) s += x0[i * EMB + j] * W0[o * EMB + j];
        xh[t] = fmaxf(s, 0.f);
    }
    __syncthreads();

    // xt = A @ xh
    if (t < N_NODES * HID) {
        const int i = t / HID, o = t % HID;
        float s = 0.f;
        #pragma unroll
        for (int k = 0; k < N_NODES; k++) s += sA[i * N_NODES + k] * xh[k * HID + o];
        xt[t] = s;
    }
    __syncthreads();

    // xh = relu(xt @ W1^T)
    if (t < N_NODES * HID) {
        const int i = t / HID, o = t % HID;
        float s = 0.f;
        #pragma unroll
        for (int j = 0; j < HID; j++) s += xt[i * HID + j] * W1[o * HID + j];
        xh[t] = fmaxf(s, 0.f);
    }
    __syncthreads();

    // xt = A @ xh
    if (t < N_NODES * HID) {
        const int i = t / HID, o = t % HID;
        float s = 0.f;
        #pragma unroll
        for (int k = 0; k < N_NODES; k++) s += sA[i * N_NODES + k] * xh[k * HID + o];
        xt[t] = s;
    }
    __syncthreads();

    // xh = relu(xt @ W2^T)
    if (t < N_NODES * HID) {
        const int i = t / HID, o = t % HID;
        float s = 0.f;
        #pragma unroll
        for (int j = 0; j < HID; j++) s += xt[i * HID + j] * W2[o * HID + j];
        xh[t] = fmaxf(s, 0.f);
    }
    __syncthreads();

    // node_emb = xh @ Wf^T + bf              [5,16] -> lut rows 1..5
    if (t < N_NODES * EMB) {
        const int n = t / EMB, j = t % EMB;
        float s = bf[j];
        #pragma unroll
        for (int o = 0; o < HID; o++) s += xh[n * HID + o] * Wf[j * HID + o];
        g_lut[(n + 1) * EMB + j] = s;
    }
    // lut row 0 = emb_table[0] (only gse row reachable: game_state==0)
    if (t < EMB) g_lut[t] = se[t];
}

// 4 threads per cell; thread writes one float4 (16 B). Warp stores are fully
// contiguous 128B segments. LUT (6 rows x 4 float4) staged in shared.
__global__ void scatter_kernel(const int* __restrict__ gs,
                               float4* __restrict__ out,
                               int nquads /* = ncells*4 */) {
    __shared__ float4 slut[24];
    const int t = threadIdx.x;
    if (t < 24) slut[t] = reinterpret_cast<const float4*>(g_lut)[t];
    __syncthreads();

    const int idx = blockIdx.x * blockDim.x + t;
    if (idx < nquads) {
        const int cell = idx >> 2;
        const int q    = idx & 3;
        int c = gs[cell];
        c = min(max(c, 0), 5);          // data range is 0..4; clamp for safety
        out[idx] = slut[c * 4 + q];
    }
}

extern "C" void kernel_launch(void* const* d_in, const int* in_sizes, int n_in,
                              void* d_out, int out_size) {
    const int*   game_state = (const int*)  d_in[0];
    const float* emb_table  = (const float*)d_in[1];
    const float* A          = (const float*)d_in[2];
    const float* W0         = (const float*)d_in[3];
    const float* W1         = (const float*)d_in[4];
    const float* W2         = (const float*)d_in[5];
    const float* Wf         = (const float*)d_in[6];
    const float* bf         = (const float*)d_in[7];
    float4* out = (float4*)d_out;

    const int ncells = in_sizes[0];          // 256*128*128 = 4,194,304
    const int nquads = ncells * 4;           // 16,777,216 float4 stores

    gcn_precompute_kernel<<<1, 256>>>(emb_table, A, W0, W1, W2, Wf, bf);

    const int threads = 256;
    const int blocks  = (nquads + threads - 1) / threads;
    scatter_kernel<<<blocks, threads>>>(game_state, out, nquads);
}

// round 2
// speedup vs baseline: 1.2988x; 1.2988x over previous
#include <cuda_runtime.h>

#define N_NODES 5
#define EMB 16
#define HID 32

// LUT row c = output row for cells with game_state == c.
// Row 0 = emb_table[0]; rows 1..5 = node_emb[0..4].
__device__ float g_lut[6 * EMB];

__global__ void gcn_precompute_kernel(const float* __restrict__ emb,
                                      const float* __restrict__ A,
                                      const float* __restrict__ W0,
                                      const float* __restrict__ W1,
                                      const float* __restrict__ W2,
                                      const float* __restrict__ Wf,
                                      const float* __restrict__ bf) {
    __shared__ float sA[N_NODES * N_NODES];
    __shared__ float se[N_NODES * EMB];
    __shared__ float sW0[HID * EMB];
    __shared__ float sW1[HID * HID];
    __shared__ float sW2[HID * HID];
    __shared__ float sWf[EMB * HID];
    __shared__ float sbf[EMB];
    __shared__ float x0[N_NODES * EMB];
    __shared__ float xh[N_NODES * HID];
    __shared__ float xt[N_NODES * HID];
    const int t = threadIdx.x;
    const int nt = blockDim.x;

    // Coalesced cooperative staging of all parameters (high MLP).
    for (int i = t; i < N_NODES * N_NODES; i += nt) sA[i] = A[i];
    for (int i = t; i < N_NODES * EMB;     i += nt) se[i]  = emb[i];
    for (int i = t; i < HID * EMB;         i += nt) sW0[i] = W0[i];
    for (int i = t; i < HID * HID;         i += nt) sW1[i] = W1[i];
    for (int i = t; i < HID * HID;         i += nt) sW2[i] = W2[i];
    for (int i = t; i < EMB * HID;         i += nt) sWf[i] = Wf[i];
    for (int i = t; i < EMB;               i += nt) sbf[i] = bf[i];
    __syncthreads();

    // x0 = A @ emb_table                     [5,16]
    if (t < N_NODES * EMB) {
        const int i = t / EMB, j = t % EMB;
        float s = 0.f;
        #pragma unroll
        for (int k = 0; k < N_NODES; k++) s += sA[i * N_NODES + k] * se[k * EMB + j];
        x0[t] = s;
    }
    __syncthreads();

    // xh = relu(x0 @ W0^T)                   [5,32]
    if (t < N_NODES * HID) {
        const int i = t / HID, o = t % HID;
        float s = 0.f;
        #pragma unroll
        for (int j = 0; j < EMB; j++) s += x0[i * EMB + j] * sW0[o * EMB + j];
        xh[t] = fmaxf(s, 0.f);
    }
    __syncthreads();

    // xt = A @ xh
    if (t < N_NODES * HID) {
        const int i = t / HID, o = t % HID;
        float s = 0.f;
        #pragma unroll
        for (int k = 0; k < N_NODES; k++) s += sA[i * N_NODES + k] * xh[k * HID + o];
        xt[t] = s;
    }
    __syncthreads();

    // xh = relu(xt @ W1^T)
    if (t < N_NODES * HID) {
        const int i = t / HID, o = t % HID;
        float s = 0.f;
        #pragma unroll
        for (int j = 0; j < HID; j++) s += xt[i * HID + j] * sW1[o * HID + j];
        xh[t] = fmaxf(s, 0.f);
    }
    __syncthreads();

    // xt = A @ xh
    if (t < N_NODES * HID) {
        const int i = t / HID, o = t % HID;
        float s = 0.f;
        #pragma unroll
        for (int k = 0; k < N_NODES; k++) s += sA[i * N_NODES + k] * xh[k * HID + o];
        xt[t] = s;
    }
    __syncthreads();

    // xh = relu(xt @ W2^T)
    if (t < N_NODES * HID) {
        const int i = t / HID, o = t % HID;
        float s = 0.f;
        #pragma unroll
        for (int j = 0; j < HID; j++) s += xt[i * HID + j] * sW2[o * HID + j];
        xh[t] = fmaxf(s, 0.f);
    }
    __syncthreads();

    // node_emb = xh @ Wf^T + bf              [5,16] -> lut rows 1..5
    if (t < N_NODES * EMB) {
        const int n = t / EMB, j = t % EMB;
        float s = sbf[j];
        #pragma unroll
        for (int o = 0; o < HID; o++) s += xh[n * HID + o] * sWf[j * HID + o];
        g_lut[(n + 1) * EMB + j] = s;
    }
    // lut row 0 = emb_table[0] (only gse row reachable: game_state==0)
    if (t < EMB) g_lut[t] = se[t];
}

// One thread per CELL. Thread loads c once; warp then issues 4 independent,
// perfectly coalesced STG.128 passes over its 128-quad (2 KB) output segment.
// LUT row for store k, lane l comes from lane 8k+(l>>2) via shfl.
__global__ void scatter_kernel(const int* __restrict__ gs,
                               float4* __restrict__ out,
                               int ncells) {
    __shared__ float4 slut[24];
    const int t = threadIdx.x;
    if (t < 24) slut[t] = reinterpret_cast<const float4*>(g_lut)[t];
    __syncthreads();

    const int cell = blockIdx.x * blockDim.x + t;
    int c = 0;
    if (cell < ncells) {
        c = gs[cell];
        c = min(max(c, 0), 5);
    }

    const int lane = t & 31;
    // first quad this warp writes, offset by lane
    const unsigned warp_cell0 = (unsigned)(blockIdx.x * blockDim.x + (t & ~31));
    const unsigned base = warp_cell0 * 4u + (unsigned)lane;
    const unsigned nquads = (unsigned)ncells * 4u;

    #pragma unroll
    for (int k = 0; k < 4; k++) {
        const int src = 8 * k + (lane >> 2);
        const int ck = __shfl_sync(0xffffffffu, c, src);
        const unsigned q = base + 32u * k;
        if (q < nquads)
            out[q] = slut[ck * 4 + (lane & 3)];
    }
}

extern "C" void kernel_launch(void* const* d_in, const int* in_sizes, int n_in,
                              void* d_out, int out_size) {
    const int*   game_state = (const int*)  d_in[0];
    const float* emb_table  = (const float*)d_in[1];
    const float* A          = (const float*)d_in[2];
    const float* W0         = (const float*)d_in[3];
    const float* W1         = (const float*)d_in[4];
    const float* W2         = (const float*)d_in[5];
    const float* Wf         = (const float*)d_in[6];
    const float* bf         = (const float*)d_in[7];
    float4* out = (float4*)d_out;

    const int ncells = in_sizes[0];          // 256*128*128 = 4,194,304

    gcn_precompute_kernel<<<1, 256>>>(emb_table, A, W0, W1, W2, Wf, bf);

    const int threads = 256;
    const int blocks  = (ncells + threads - 1) / threads;
    scatter_kernel<<<blocks, threads>>>(game_state, out, ncells);
}

// round 3
// speedup vs baseline: 1.2995x; 1.0005x over previous
#include <cuda_runtime.h>

#define N_NODES 5
#define EMB 16
#define HID 32

// LUT row c = output row for cells with game_state == c.
// Row 0 = emb_table[0]; rows 1..5 = node_emb[0..4].
__device__ float g_lut[6 * EMB];

__global__ void gcn_precompute_kernel(const float* __restrict__ emb,
                                      const float* __restrict__ A,
                                      const float* __restrict__ W0,
                                      const float* __restrict__ W1,
                                      const float* __restrict__ W2,
                                      const float* __restrict__ Wf,
                                      const float* __restrict__ bf) {
    __shared__ float sA[N_NODES * N_NODES];
    __shared__ float se[N_NODES * EMB];
    __shared__ float sW0[HID * EMB];
    __shared__ float sW1[HID * HID];
    __shared__ float sW2[HID * HID];
    __shared__ float sWf[EMB * HID];
    __shared__ float sbf[EMB];
    __shared__ float x0[N_NODES * EMB];
    __shared__ float xh[N_NODES * HID];
    __shared__ float xt[N_NODES * HID];
    const int t = threadIdx.x;
    const int nt = blockDim.x;

    // Coalesced cooperative staging of all parameters (high MLP).
    for (int i = t; i < N_NODES * N_NODES; i += nt) sA[i] = A[i];
    for (int i = t; i < N_NODES * EMB;     i += nt) se[i]  = emb[i];
    for (int i = t; i < HID * EMB;         i += nt) sW0[i] = W0[i];
    for (int i = t; i < HID * HID;         i += nt) sW1[i] = W1[i];
    for (int i = t; i < HID * HID;         i += nt) sW2[i] = W2[i];
    for (int i = t; i < EMB * HID;         i += nt) sWf[i] = Wf[i];
    for (int i = t; i < EMB;               i += nt) sbf[i] = bf[i];
    __syncthreads();

    // x0 = A @ emb_table                     [5,16]
    if (t < N_NODES * EMB) {
        const int i = t / EMB, j = t % EMB;
        float s = 0.f;
        #pragma unroll
        for (int k = 0; k < N_NODES; k++) s += sA[i * N_NODES + k] * se[k * EMB + j];
        x0[t] = s;
    }
    __syncthreads();

    // xh = relu(x0 @ W0^T)                   [5,32]
    if (t < N_NODES * HID) {
        const int i = t / HID, o = t % HID;
        float s = 0.f;
        #pragma unroll
        for (int j = 0; j < EMB; j++) s += x0[i * EMB + j] * sW0[o * EMB + j];
        xh[t] = fmaxf(s, 0.f);
    }
    __syncthreads();

    // xt = A @ xh
    if (t < N_NODES * HID) {
        const int i = t / HID, o = t % HID;
        float s = 0.f;
        #pragma unroll
        for (int k = 0; k < N_NODES; k++) s += sA[i * N_NODES + k] * xh[k * HID + o];
        xt[t] = s;
    }
    __syncthreads();

    // xh = relu(xt @ W1^T)
    if (t < N_NODES * HID) {
        const int i = t / HID, o = t % HID;
        float s = 0.f;
        #pragma unroll
        for (int j = 0; j < HID; j++) s += xt[i * HID + j] * sW1[o * HID + j];
        xh[t] = fmaxf(s, 0.f);
    }
    __syncthreads();

    // xt = A @ xh
    if (t < N_NODES * HID) {
        const int i = t / HID, o = t % HID;
        float s = 0.f;
        #pragma unroll
        for (int k = 0; k < N_NODES; k++) s += sA[i * N_NODES + k] * xh[k * HID + o];
        xt[t] = s;
    }
    __syncthreads();

    // xh = relu(xt @ W2^T)
    if (t < N_NODES * HID) {
        const int i = t / HID, o = t % HID;
        float s = 0.f;
        #pragma unroll
        for (int j = 0; j < HID; j++) s += xt[i * HID + j] * sW2[o * HID + j];
        xh[t] = fmaxf(s, 0.f);
    }
    __syncthreads();

    // node_emb = xh @ Wf^T + bf              [5,16] -> lut rows 1..5
    if (t < N_NODES * EMB) {
        const int n = t / EMB, j = t % EMB;
        float s = sbf[j];
        #pragma unroll
        for (int o = 0; o < HID; o++) s += xh[n * HID + o] * sWf[j * HID + o];
        g_lut[(n + 1) * EMB + j] = s;
    }
    // lut row 0 = emb_table[0] (only gse row reachable: game_state==0)
    if (t < EMB) g_lut[t] = se[t];
}

// One thread per CELL. Thread loads c once; warp then issues 4 independent,
// perfectly coalesced STG.128 passes over its 128-quad (2 KB) output segment.
// LUT row for store k, lane l comes from lane 8k+(l>>2) via shfl.
__global__ void scatter_kernel(const int* __restrict__ gs,
                               float4* __restrict__ out,
                               int ncells) {
    __shared__ float4 slut[24];
    const int t = threadIdx.x;
    if (t < 24) slut[t] = reinterpret_cast<const float4*>(g_lut)[t];
    __syncthreads();

    const int cell = blockIdx.x * blockDim.x + t;
    int c = 0;
    if (cell < ncells) {
        c = gs[cell];
        c = min(max(c, 0), 5);
    }

    const int lane = t & 31;
    // first quad this warp writes, offset by lane
    const unsigned warp_cell0 = (unsigned)(blockIdx.x * blockDim.x + (t & ~31));
    const unsigned base = warp_cell0 * 4u + (unsigned)lane;
    const unsigned nquads = (unsigned)ncells * 4u;

    #pragma unroll
    for (int k = 0; k < 4; k++) {
        const int src = 8 * k + (lane >> 2);
        const int ck = __shfl_sync(0xffffffffu, c, src);
        const unsigned q = base + 32u * k;
        if (q < nquads)
            out[q] = slut[ck * 4 + (lane & 3)];
    }
}

extern "C" void kernel_launch(void* const* d_in, const int* in_sizes, int n_in,
                              void* d_out, int out_size) {
    const int*   game_state = (const int*)  d_in[0];
    const float* emb_table  = (const float*)d_in[1];
    const float* A          = (const float*)d_in[2];
    const float* W0         = (const float*)d_in[3];
    const float* W1         = (const float*)d_in[4];
    const float* W2         = (const float*)d_in[5];
    const float* Wf         = (const float*)d_in[6];
    const float* bf         = (const float*)d_in[7];
    float4* out = (float4*)d_out;

    const int ncells = in_sizes[0];          // 256*128*128 = 4,194,304

    gcn_precompute_kernel<<<1, 256>>>(emb_table, A, W0, W1, W2, Wf, bf);

    const int threads = 256;
    const int blocks  = (ncells + threads - 1) / threads;
    scatter_kernel<<<blocks, threads>>>(game_state, out, ncells);
}